// round 2
// baseline (speedup 1.0000x reference)
#include <cuda_runtime.h>
#include <cstdint>

#define N_QUERIES 262144
#define N_SLOTS   1024
#define KEY_DIM   64
#define VAL_DIM   64
#define TOPK      4
#define LR        0.001f
#define MOMENTUM  0.9f
#define WD        0.0001f

#define RET_ELEMS  (N_QUERIES * TOPK * VAL_DIM)   // 67108864
#define SLOT_ELEMS (N_SLOTS * VAL_DIM)            // 65536

// ---------------- scratch (device globals: no allocation allowed) ----------
__device__ int   g_idx[N_QUERIES * TOPK];                     // 4 MB
__device__ __align__(16) float g_sg[SLOT_ELEMS];              // slot grad sums
__device__ float g_cnt[N_SLOTS];                              // slot counts
// pair-interleaved keys: [tile(8)][k(64)][pair(64)] as u64 (lo=slot 2p, hi=2p+1)
__device__ __align__(16) unsigned long long g_kp[8 * 64 * 64];  // 256 KB

// ---------------- f32x2 packed fma (per-lane independent fp32 FMA) ---------
__device__ __forceinline__ unsigned long long fma2(unsigned long long a,
                                                   unsigned long long b,
                                                   unsigned long long c) {
    unsigned long long d;
    asm("fma.rn.f32x2 %0, %1, %2, %3;" : "=l"(d) : "l"(a), "l"(b), "l"(c));
    return d;
}

// ---------------- kernel 0: zero accumulators + pack keys -------------------
__global__ void prep_kernel(const float* __restrict__ keys) {
    int i = blockIdx.x * blockDim.x + threadIdx.x;   // grid covers 65536
    if (i < SLOT_ELEMS) g_sg[i] = 0.0f;
    if (i < N_SLOTS)    g_cnt[i] = 0.0f;
    if (i < 8 * 64 * 64) {
        int tile = i >> 12;
        int k    = (i >> 6) & 63;
        int p    = i & 63;
        int s0   = tile * 128 + 2 * p;
        unsigned lo = __float_as_uint(keys[s0 * KEY_DIM + k]);
        unsigned hi = __float_as_uint(keys[(s0 + 1) * KEY_DIM + k]);
        g_kp[i] = ((unsigned long long)hi << 32) | lo;
    }
}

// ---------------- kernel 1: sim + exact top-4 + gather retrieved ------------
// One thread per query. sim[q][slot] computed as a SINGLE sequential fp32 FMA
// chain over k=0..63 (matches Eigen/cublas single-accumulator order), packed
// two slots per f32x2 lane-pair. Keys broadcast from SMEM (warp-uniform),
// queries in SMEM transposed [k][tid] (conflict-free).
__global__ void __launch_bounds__(256, 2)
simtopk_kernel(const float* __restrict__ queries,
               const float* __restrict__ vals,
               float* __restrict__ retrieved) {
    extern __shared__ char smem[];
    unsigned long long* ksh = (unsigned long long*)smem;            // 32 KB: [k][pair]
    float*              qsh = (float*)(smem + 64 * 64 * 8);         // 64 KB: [k][tid]

    const int tid = threadIdx.x;
    const int q   = blockIdx.x * 256 + tid;

    // stage query into SMEM transposed: qsh[k*256 + tid]
    {
        const float4* qrow = (const float4*)(queries + (size_t)q * KEY_DIM);
#pragma unroll
        for (int i = 0; i < 16; i++) {
            float4 v = qrow[i];
            qsh[(4 * i + 0) * 256 + tid] = v.x;
            qsh[(4 * i + 1) * 256 + tid] = v.y;
            qsh[(4 * i + 2) * 256 + tid] = v.z;
            qsh[(4 * i + 3) * 256 + tid] = v.w;
        }
    }

    float tv0 = -1e30f, tv1 = -1e30f, tv2 = -1e30f, tv3 = -1e30f;
    int   ti0 = 0, ti1 = 0, ti2 = 0, ti3 = 0;

    for (int tile = 0; tile < 8; tile++) {
        __syncthreads();
        {   // cooperative load of packed key tile (32 KB contiguous)
            const float4* kg  = (const float4*)(g_kp + tile * 4096);
            float4*       ks4 = (float4*)ksh;
            for (int t = tid; t < 2048; t += 256) ks4[t] = kg[t];
        }
        __syncthreads();

        const ulonglong2* ksh2 = (const ulonglong2*)ksh;
        for (int pg = 0; pg < 8; pg++) {        // 8 pairs (16 slots) per group
            unsigned long long a0 = 0ull, a1 = 0ull, a2 = 0ull, a3 = 0ull;
            unsigned long long a4 = 0ull, a5 = 0ull, a6 = 0ull, a7 = 0ull;
#pragma unroll 8
            for (int k = 0; k < 64; k++) {
                float qk = qsh[k * 256 + tid];
                unsigned long long qd;
                asm("mov.b64 %0, {%1, %1};" : "=l"(qd) : "f"(qk));
                int base = k * 32 + pg * 4;     // ulonglong2 index
                ulonglong2 c0 = ksh2[base + 0];
                ulonglong2 c1 = ksh2[base + 1];
                ulonglong2 c2 = ksh2[base + 2];
                ulonglong2 c3 = ksh2[base + 3];
                a0 = fma2(qd, c0.x, a0);
                a1 = fma2(qd, c0.y, a1);
                a2 = fma2(qd, c1.x, a2);
                a3 = fma2(qd, c1.y, a3);
                a4 = fma2(qd, c2.x, a4);
                a5 = fma2(qd, c2.y, a5);
                a6 = fma2(qd, c3.x, a6);
                a7 = fma2(qd, c3.y, a7);
            }
            unsigned long long accs[8] = {a0, a1, a2, a3, a4, a5, a6, a7};
            int sbase = tile * 128 + pg * 16;
#pragma unroll
            for (int pp = 0; pp < 8; pp++) {
#pragma unroll
                for (int h = 0; h < 2; h++) {
                    float sv = (h == 0)
                        ? __uint_as_float((unsigned)accs[pp])
                        : __uint_as_float((unsigned)(accs[pp] >> 32));
                    int jg = sbase + 2 * pp + h;
                    // strict > : ties keep earlier index (stable top_k)
                    if (sv > tv3) {
                        if (sv > tv0) {
                            tv3 = tv2; ti3 = ti2;
                            tv2 = tv1; ti2 = ti1;
                            tv1 = tv0; ti1 = ti0;
                            tv0 = sv;  ti0 = jg;
                        } else if (sv > tv1) {
                            tv3 = tv2; ti3 = ti2;
                            tv2 = tv1; ti2 = ti1;
                            tv1 = sv;  ti1 = jg;
                        } else if (sv > tv2) {
                            tv3 = tv2; ti3 = ti2;
                            tv2 = sv;  ti2 = jg;
                        } else {
                            tv3 = sv;  ti3 = jg;
                        }
                    }
                }
            }
        }
    }

    // write indices + gather retrieved rows (vals is L2-resident, 256 KB)
    int ids[4] = {ti0, ti1, ti2, ti3};
    float4* out4 = (float4*)(retrieved + (size_t)q * (TOPK * VAL_DIM));
#pragma unroll
    for (int k = 0; k < TOPK; k++) {
        g_idx[q * TOPK + k] = ids[k];
        const float4* vr = (const float4*)(vals + (size_t)ids[k] * VAL_DIM);
#pragma unroll
        for (int t = 0; t < 16; t++) out4[k * 16 + t] = vr[t];
    }
}

// ---------------- kernel 2: scatter grads into slot accumulators ------------
// gridDim = (128 chunks, 8 column-groups). Each CTA pre-reduces its chunk's
// grads into a 1024x8 SMEM table (32 KB), then flushes with red.global.v4.f32.
__global__ void __launch_bounds__(256)
scatter_kernel(const float* __restrict__ grads) {
    __shared__ float sg[N_SLOTS * 8];     // 32 KB
    __shared__ int   scnt[N_SLOTS];       //  4 KB (only used by cg==0)

    const int cg    = blockIdx.y;                   // cols cg*8 .. cg*8+7
    const int chunk = blockIdx.x;                   // 8192 entries per chunk
    for (int t = threadIdx.x; t < N_SLOTS * 8; t += 256) sg[t] = 0.0f;
    if (cg == 0)
        for (int t = threadIdx.x; t < N_SLOTS; t += 256) scnt[t] = 0;
    __syncthreads();

    const int lane  = threadIdx.x & 31;
    const int warp  = threadIdx.x >> 5;
    const int ebase = chunk * 8192;

    for (int it = 0; it < 64; it++) {
        int e    = ebase + warp * 1024 + it * 16 + (lane >> 1);
        int slot = g_idx[e];
        int coff = (lane & 1) * 4;
        float4 g = *(const float4*)(grads + (size_t)e * VAL_DIM + cg * 8 + coff);
        atomicAdd(&sg[slot * 8 + coff + 0], g.x);
        atomicAdd(&sg[slot * 8 + coff + 1], g.y);
        atomicAdd(&sg[slot * 8 + coff + 2], g.z);
        atomicAdd(&sg[slot * 8 + coff + 3], g.w);
        if (cg == 0 && (lane & 1) == 0) atomicAdd(&scnt[slot], 1);
    }
    __syncthreads();

    for (int t = threadIdx.x; t < 2048; t += 256) {
        int slot = t >> 1;
        int part = (t & 1) * 4;
        float*  dst = &g_sg[slot * VAL_DIM + cg * 8 + part];
        float4  v   = *(float4*)&sg[slot * 8 + part];
        asm volatile("red.global.add.v4.f32 [%0], {%1, %2, %3, %4};"
                     :: "l"(dst), "f"(v.x), "f"(v.y), "f"(v.z), "f"(v.w)
                     : "memory");
    }
    if (cg == 0)
        for (int t = threadIdx.x; t < N_SLOTS; t += 256)
            atomicAdd(&g_cnt[t], (float)scnt[t]);
}

// ---------------- kernel 3: finalize vals_new / mom_new ---------------------
__global__ void finalize_kernel(const float* __restrict__ vals,
                                const float* __restrict__ mom,
                                float* __restrict__ out) {
    int i = blockIdx.x * blockDim.x + threadIdx.x;   // 0..65535
    if (i >= SLOT_ELEMS) return;
    int   slot = i >> 6;
    float c    = g_cnt[slot];
    float sgv  = g_sg[i];
    bool  nz   = c > 0.0f;
    float avg  = nz ? (sgv / c) : sgv;
    float mn   = MOMENTUM * mom[i] + avg;
    float delta = -LR * (mn + WD * vals[i]);
    float vn   = vals[i] + (nz ? delta : 0.0f);
    out[RET_ELEMS + i]              = vn;            // vals_new
    out[RET_ELEMS + SLOT_ELEMS + i] = mn;            // mom_new
}

// ---------------- launch ----------------------------------------------------
extern "C" void kernel_launch(void* const* d_in, const int* in_sizes, int n_in,
                              void* d_out, int out_size) {
    const float* queries = (const float*)d_in[0];
    const float* keys    = (const float*)d_in[1];
    const float* vals    = (const float*)d_in[2];
    const float* mom     = (const float*)d_in[3];
    const float* grads   = (const float*)d_in[4];
    float* out = (float*)d_out;

    // 96 KB dynamic smem for simtopk (32 KB keys + 64 KB queries)
    static bool attr_set = false;
    if (!attr_set) {
        cudaFuncSetAttribute(simtopk_kernel,
                             cudaFuncAttributeMaxDynamicSharedMemorySize,
                             96 * 1024);
        attr_set = true;
    }

    prep_kernel<<<256, 256>>>(keys);
    simtopk_kernel<<<N_QUERIES / 256, 256, 96 * 1024>>>(queries, vals, out);
    scatter_kernel<<<dim3(128, 8), 256>>>(grads);
    finalize_kernel<<<256, 256>>>(vals, mom, out);
}